// round 8
// baseline (speedup 1.0000x reference)
#include <cuda_runtime.h>

#define MAX_NE 50048
#define MAX_NR 1024
#define MAX_E  800000
#define EH 256
#define RH 64
#define SCAN_B 512

// -------- scratch (device globals; no allocation allowed) --------
__device__ float    g_seh[MAX_NE];
__device__ float    g_set[MAX_NE];
__device__ float    g_sr [MAX_NR];
__device__ unsigned g_Menc;            // encoded max over s_r
__device__ int      g_arrive;          // grid-barrier arrival counter
__device__ int      g_cnth[MAX_NE];
__device__ int      g_cntt[MAX_NE];
__device__ int      g_offh[MAX_NE];
__device__ int      g_offt[MAX_NE];
__device__ int      g_curh[MAX_NE];
__device__ int      g_curt[MAX_NE];
__device__ int      g_bsumh[SCAN_B];
__device__ int      g_bsumt[SCAN_B];
__device__ int      g_adjh[MAX_E];     // rel index per CSR slot, head-sorted
__device__ int      g_adjt[MAX_E];     // tail-sorted

// Order-preserving float<->uint map so atomicMax(unsigned) == float max.
__device__ __forceinline__ unsigned enc_f(float f) {
    unsigned u = __float_as_uint(f);
    return (u & 0x80000000u) ? ~u : (u | 0x80000000u);
}
__device__ __forceinline__ float dec_f(unsigned u) {
    u = (u & 0x80000000u) ? (u & 0x7FFFFFFFu) : ~u;
    return __uint_as_float(u);
}
__device__ __forceinline__ float leaky(float x) { return x > 0.f ? x : 0.01f * x; }

// ---------------- K0: init (zero counts + barrier counter) ----------------
__global__ void k_init(int nE) {
    int i = blockIdx.x * blockDim.x + threadIdx.x;
    if (i == 0) { g_Menc = 0u; g_arrive = 0; }
    if (i < nE) { g_cnth[i] = 0; g_cntt[i] = 0; }
}

// ---------------- K1: node scores + rel scores + edge histogram, fused ----------------
__global__ void k_phase1(const float* __restrict__ xe,
                         const float* __restrict__ xr,
                         const float* __restrict__ ah,
                         const float* __restrict__ at,
                         const float* __restrict__ ar,
                         const int* __restrict__ ei,
                         int nE, int nR, int E,
                         int nodeBlocks, int relBlocks) {
    int b = blockIdx.x;
    int lane = threadIdx.x & 31;
    int warpInBlk = threadIdx.x >> 5;
    if (b < nodeBlocks) {
        // --- per-node scores: warp per node, float4 loads ---
        int n = b * 8 + warpInBlk;
        if (n >= nE) return;
        const float4* row = reinterpret_cast<const float4*>(xe + (size_t)n * EH);
        const float4* a4h = reinterpret_cast<const float4*>(ah);
        const float4* a4t = reinterpret_cast<const float4*>(at);
        float sh = 0.f, st = 0.f;
#pragma unroll
        for (int j = 0; j < 2; j++) {
            float4 v = row[lane + 32 * j];
            float4 wh = a4h[lane + 32 * j];
            float4 wt = a4t[lane + 32 * j];
            sh = fmaf(v.x, wh.x, fmaf(v.y, wh.y, fmaf(v.z, wh.z, fmaf(v.w, wh.w, sh))));
            st = fmaf(v.x, wt.x, fmaf(v.y, wt.y, fmaf(v.z, wt.z, fmaf(v.w, wt.w, st))));
        }
#pragma unroll
        for (int o = 16; o; o >>= 1) {
            sh += __shfl_xor_sync(0xFFFFFFFFu, sh, o);
            st += __shfl_xor_sync(0xFFFFFFFFu, st, o);
        }
        if (lane == 0) { g_seh[n] = sh; g_set[n] = st; }
    } else if (b < nodeBlocks + relBlocks) {
        // --- per-relation scores + global max ---
        int r = (b - nodeBlocks) * 8 + warpInBlk;
        if (r >= nR) return;
        const float* row = xr + (size_t)r * RH;
        float s = fmaf(row[lane], ar[lane], row[lane + 32] * ar[lane + 32]);
#pragma unroll
        for (int o = 16; o; o >>= 1) s += __shfl_xor_sync(0xFFFFFFFFu, s, o);
        if (lane == 0) {
            g_sr[r] = s;
            atomicMax(&g_Menc, enc_f(s));
        }
    } else {
        // --- edge histogram ---
        int e = (b - nodeBlocks - relBlocks) * 256 + threadIdx.x;
        if (e >= E) return;
        atomicAdd(&g_cnth[ei[e]], 1);
        atomicAdd(&g_cntt[ei[E + e]], 1);
    }
}

// ---------------- shuffle-based exclusive block scan helper ----------------
__device__ __forceinline__ int block_exscan(int v, int* warp_sums, int* p_total) {
    int lane = threadIdx.x & 31;
    int wid = threadIdx.x >> 5;
    int x = v;
#pragma unroll
    for (int o = 1; o < 32; o <<= 1) {
        int y = __shfl_up_sync(0xFFFFFFFFu, x, o);
        if (lane >= o) x += y;
    }
    if (lane == 31) warp_sums[wid] = x;
    __syncthreads();
    if (wid == 0) {
        int nw = blockDim.x >> 5;
        int ws = (lane < nw) ? warp_sums[lane] : 0;
#pragma unroll
        for (int o = 1; o < 32; o <<= 1) {
            int y = __shfl_up_sync(0xFFFFFFFFu, ws, o);
            if (lane >= o) ws += y;
        }
        if (lane < nw) warp_sums[lane] = ws;
        if (lane == (nw - 1)) *p_total = ws;
    }
    __syncthreads();
    int base = (wid > 0) ? warp_sums[wid - 1] : 0;
    return base + x - v;
}

// ---------------- K2: fused global scan (single launch, grid barrier) ----------------
__global__ void k_scan(int nE, int nB) {
    __shared__ int wsum[16];
    __shared__ int tot;
    __shared__ int basep[2];
    int b = blockIdx.x;
    int i = b * SCAN_B + threadIdx.x;

    int vh = (i < nE) ? g_cnth[i] : 0;
    int exh = block_exscan(vh, wsum, &tot);
    if (threadIdx.x == 0) g_bsumh[b] = tot;
    __syncthreads();
    int vt = (i < nE) ? g_cntt[i] : 0;
    int ext = block_exscan(vt, wsum, &tot);
    if (threadIdx.x == 0) g_bsumt[b] = tot;

    __threadfence();
    __syncthreads();
    if (threadIdx.x == 0) {
        atomicAdd(&g_arrive, 1);
        while (atomicAdd(&g_arrive, 0) < nB) { }
    }
    __syncthreads();

    if (threadIdx.x < 32) {
        int ph = 0, pt = 0;
        for (int k = threadIdx.x; k < b; k += 32) { ph += g_bsumh[k]; pt += g_bsumt[k]; }
#pragma unroll
        for (int o = 16; o; o >>= 1) {
            ph += __shfl_xor_sync(0xFFFFFFFFu, ph, o);
            pt += __shfl_xor_sync(0xFFFFFFFFu, pt, o);
        }
        if (threadIdx.x == 0) { basep[0] = ph; basep[1] = pt; }
    }
    __syncthreads();

    if (i < nE) {
        int oh = basep[0] + exh;
        int ot = basep[1] + ext;
        g_offh[i] = oh; g_curh[i] = oh;
        g_offt[i] = ot; g_curt[i] = ot;
    }
}

// ---------------- K3: fill CSR slots with rel only (no score gathers) ----------------
__global__ void k_fill(const int* __restrict__ ei,
                       const int* __restrict__ rel, int E) {
    int e = blockIdx.x * blockDim.x + threadIdx.x;
    if (e >= E) return;
    int h = ei[e];
    int t = ei[E + e];
    int r = rel[e];
    int p = atomicAdd(&g_curh[h], 1);
    g_adjh[p] = r;
    int q = atomicAdd(&g_curt[t], 1);
    g_adjt[q] = r;
}

// ---------------- K4: half-warp-split gather with inline softmax ----------------
__global__ void k_gather(const float* __restrict__ xr,
                         float* __restrict__ out, int nE) {
    int n = (blockIdx.x * blockDim.x + threadIdx.x) >> 5;
    int lane = threadIdx.x & 31;
    if (n >= nE) return;

    bool isHead = lane < 16;
    int k = lane & 15;                       // float4 index within the 64-dim row

    int degh = g_cnth[n], bh = g_offh[n];
    int degt = g_cntt[n], bt = g_offt[n];
    int deg  = isHead ? degh : degt;
    int base = isHead ? bh : bt;
    const int* adj = isHead ? g_adjh : g_adjt;
    int dmax = max(degh, degt);

    float s = isHead ? g_seh[n] : g_set[n];  // loop-invariant node score
    float M = dec_f(g_Menc);
    float B = leaky(s + M);                  // per-node stabilizer bound

    float4 acc = make_float4(0.f, 0.f, 0.f, 0.f);
    float den = 0.f;
    const float4* xr4 = reinterpret_cast<const float4*>(xr);

    // software-pipelined: prefetch next rel while current row load is in flight
    int rcur = (0 < deg) ? adj[base] : 0;
    for (int j = 0; j < dmax; j++) {
        int rnext = (j + 1 < deg) ? adj[base + j + 1] : 0;
        if (j < deg) {
            float sr = g_sr[rcur];           // 4KB table, L1-resident
            float w = __expf(leaky(s + sr) - B);
            den += w;                        // identical in all 16 lanes of the half
            float4 m = xr4[rcur * (RH / 4) + k];
            acc.x = fmaf(w, m.x, acc.x);
            acc.y = fmaf(w, m.y, acc.y);
            acc.z = fmaf(w, m.z, acc.z);
            acc.w = fmaf(w, m.w, acc.w);
        }
        rcur = rnext;
    }

    float inv = (den > 0.f) ? 1.0f / den : 0.f;
    float4* o4 = reinterpret_cast<float4*>(out + (size_t)n * (2 * RH));
    // head half writes float4 slots 0..15 (dims [0,64)), tail half 16..31 (dims [64,128))
    o4[lane] = make_float4(acc.x * inv, acc.y * inv, acc.z * inv, acc.w * inv);
}

// ---------------- launch ----------------
extern "C" void kernel_launch(void* const* d_in, const int* in_sizes, int n_in,
                              void* d_out, int out_size) {
    const float* xe  = (const float*)d_in[0];
    const float* xr  = (const float*)d_in[1];
    const int*   ei  = (const int*)d_in[2];   // int32 (JAX x64 disabled)
    const int*   rel = (const int*)d_in[3];
    // d_in[4], d_in[5] (line graph) unused by the reference output
    const float* ahw = (const float*)d_in[6];
    const float* atw = (const float*)d_in[7];
    const float* arw = (const float*)d_in[8];

    int nE = in_sizes[0] / EH;   // 50000
    int nR = in_sizes[1] / RH;   // 1000
    int E  = in_sizes[3];        // 800000
    if (nE > MAX_NE) nE = MAX_NE;
    if (nR > MAX_NR) nR = MAX_NR;
    if (E  > MAX_E)  E  = MAX_E;

    float* out = (float*)d_out;

    int nodeBlocks = (nE + 7) / 8;
    int relBlocks  = (nR + 7) / 8;
    int histBlocks = (E + 255) / 256;
    int nB = (nE + SCAN_B - 1) / SCAN_B;   // 98 <= 148 SMs (single wave, barrier safe)

    k_init<<<(nE + 255) / 256, 256>>>(nE);
    k_phase1<<<nodeBlocks + relBlocks + histBlocks, 256>>>(
        xe, xr, ahw, atw, arw, ei, nE, nR, E, nodeBlocks, relBlocks);
    k_scan<<<nB, SCAN_B>>>(nE, nB);
    k_fill<<<(E + 255) / 256, 256>>>(ei, rel, E);
    k_gather<<<(nE + 7) / 8, 256>>>(xr, out, nE);
}